// round 15
// baseline (speedup 1.0000x reference)
#include <cuda_runtime.h>
#include <cuda_fp16.h>
#include <math.h>

#define D 128
#define NSPLIT 32
#define CAP 128
#define MAXFLAG 512
#define T0 0.34f
#define DELTA 3e-3f        // >= 2*e for fp16 screen with fp32 accum

// ---- static scratch ----
__device__ float g_P[4096 * 128];
__device__ __half g_Ah[4096 * 128];
__device__ __half g_Qh[65536 * 128];
__device__ float g_NN[4096 * 128];
__device__ int      g_cand[4096 * CAP];
__device__ int      g_cnt[4096];
__device__ unsigned g_bestu[4096];
__device__ int   g_idx[4096];
__device__ int   g_nflag;
__device__ int   g_flaglist[MAXFLAG];
__device__ unsigned long long g_fbkey[MAXFLAG];
__device__ float g_S[16384];
__device__ float g_diag[4096];

#define TSW(r, c) (((r) * 256) + ((((c) ^ ((r) & 7))) << 4))

__device__ __forceinline__ unsigned smem_u32(const void* p) {
    unsigned a;
    asm("{ .reg .u64 t; cvta.to.shared.u64 t, %1; cvt.u32.u64 %0, t; }"
        : "=r"(a) : "l"(p));
    return a;
}
__device__ __forceinline__ void cp_async16(unsigned sm, const void* g) {
    asm volatile("cp.async.cg.shared.global [%0], [%1], 16;" :: "r"(sm), "l"(g));
}
__device__ __forceinline__ void cp_commit() {
    asm volatile("cp.async.commit_group;");
}
__device__ __forceinline__ void ldsm4(unsigned& r0, unsigned& r1, unsigned& r2,
                                      unsigned& r3, unsigned addr) {
    asm volatile("ldmatrix.sync.aligned.m8n8.x4.shared.b16 {%0,%1,%2,%3}, [%4];"
                 : "=r"(r0), "=r"(r1), "=r"(r2), "=r"(r3) : "r"(addr));
}
__device__ __forceinline__ void mma16816(float c[4], const unsigned a[4],
                                         unsigned b0, unsigned b1) {
    asm volatile("mma.sync.aligned.m16n8k16.row.col.f32.f16.f16.f32 "
                 "{%0,%1,%2,%3}, {%4,%5,%6,%7}, {%8,%9}, {%0,%1,%2,%3};"
                 : "+f"(c[0]), "+f"(c[1]), "+f"(c[2]), "+f"(c[3])
                 : "r"(a[0]), "r"(a[1]), "r"(a[2]), "r"(a[3]), "r"(b0), "r"(b1));
}
__device__ __forceinline__ unsigned ford(float f) {
    unsigned u = __float_as_uint(f);
    return (u & 0x80000000u) ? ~u : (u | 0x80000000u);
}
__device__ __forceinline__ float unford(unsigned k) {
    unsigned u = (k & 0x80000000u) ? (k ^ 0x80000000u) : ~k;
    return __uint_as_float(u);
}

// ---------------------------------------------------------------------------
// 1) normalize -> g_P fp32 + g_Ah fp16
// ---------------------------------------------------------------------------
__global__ void normalize_kernel(const float* __restrict__ p1,
                                 const float* __restrict__ p2, int B) {
    int row = blockIdx.x, l = threadIdx.x;
    const float* src = (row < B) ? (p1 + (size_t)row * D)
                                 : (p2 + (size_t)(row - B) * D);
    float4 v = ((const float4*)src)[l];
    float ss = v.x * v.x + v.y * v.y + v.z * v.z + v.w * v.w;
#pragma unroll
    for (int off = 16; off > 0; off >>= 1)
        ss += __shfl_xor_sync(0xffffffffu, ss, off);
    float inv = 1.0f / sqrtf(ss);
    float4 o = make_float4(v.x * inv, v.y * inv, v.z * inv, v.w * inv);
    ((float4*)g_P)[(size_t)row * 32 + l] = o;
    __half h[4] = {__float2half(o.x), __float2half(o.y),
                   __float2half(o.z), __float2half(o.w)};
    *(uint2*)(g_Ah + (size_t)row * D + 4 * l) = *(uint2*)h;
}

// ---------------------------------------------------------------------------
// 2) queue -> fp16, with per-call state re-init folded into blocks [0,64)
// ---------------------------------------------------------------------------
__global__ void convq_kernel(const float* __restrict__ queue) {
    int i = blockIdx.x * blockDim.x + threadIdx.x;
    if (blockIdx.x < 64) {
        int j = blockIdx.x * 256 + threadIdx.x;      // 0..16383
        g_S[j] = 0.f;
        if (j < 4096) { g_cnt[j] = 0; g_bestu[j] = 0u; }
        if (j == 0) g_nflag = 0;
    }
    float4 v = ((const float4*)queue)[i];
    __half h[4] = {__float2half(v.x), __float2half(v.y),
                   __float2half(v.z), __float2half(v.w)};
    *(uint2*)(g_Qh + 4 * (size_t)i) = *(uint2*)h;
}

// ---------------------------------------------------------------------------
// 3) NN screen: fp16 HMMA fp32-accum, M=64 tile, 3-buffer, fine splits
// ---------------------------------------------------------------------------
#define ABUF 16384
#define BUFSZ 32768
#define SMEM_NN (ABUF + 3 * BUFSZ)      // 114688

__global__ __launch_bounds__(256, 2)
void nn_kernel(int rps) {
    extern __shared__ char smem[];
    unsigned sb = smem_u32(smem);
    int tid = threadIdx.x, lane = tid & 31, wid = tid >> 5;
    int wm = wid >> 2, wn = wid & 3;
    int rowbase = blockIdx.x * 64;
    int q0 = blockIdx.y * rps;
    int nch = rps >> 7;

    int brow = tid >> 1, bh = tid & 1;
    auto issueB = [&](int ch) {
        unsigned bdst = sb + ABUF + (unsigned)(ch % 3) * BUFSZ;
        const __half* qh = g_Qh + (size_t)(q0 + ch * 128 + brow) * D;
#pragma unroll
        for (int i = 0; i < 8; i++) {
            int c = 8 * bh + i;
            cp_async16(bdst + TSW(brow, c), qh + c * 8);
        }
        cp_commit();
    };
    issueB(0);
    issueB(1);

    {
        int r = tid >> 2, qid = tid & 3;
        const uint4* sh = (const uint4*)(g_Ah + (size_t)(rowbase + r) * D);
#pragma unroll
        for (int i = 0; i < 4; i++) {
            int c = 4 * qid + i;
            *(uint4*)(smem + TSW(r, c)) = sh[c];
        }
    }

    float best[4];
#pragma unroll
    for (int s = 0; s < 4; s++) best[s] = -INFINITY;

    int a_r = ((lane >> 3) & 1) * 8 + (lane & 7);
    int a_cq = lane >> 4;
    int b_r = ((lane >> 4) << 3) + (lane & 7);
    int b_cq = (lane >> 3) & 1;

    for (int ch = 0; ch < nch; ch++) {
        if (ch + 1 < nch) asm volatile("cp.async.wait_group 1;");
        else              asm volatile("cp.async.wait_group 0;");
        __syncthreads();
        if (ch + 2 < nch) issueB(ch + 2);

        unsigned bb = sb + ABUF + (unsigned)(ch % 3) * BUFSZ;

        float acc[2][4][4];
#pragma unroll
        for (int mt = 0; mt < 2; mt++)
#pragma unroll
            for (int nt = 0; nt < 4; nt++)
#pragma unroll
                for (int e = 0; e < 4; e++) acc[mt][nt][e] = 0.f;

#pragma unroll
        for (int ks = 0; ks < 8; ks++) {
            int c0 = 2 * ks;
            unsigned bf[8];
#pragma unroll
            for (int nt2 = 0; nt2 < 2; nt2++) {
                int n = wn * 32 + nt2 * 16 + b_r;
                ldsm4(bf[4 * nt2], bf[4 * nt2 + 1], bf[4 * nt2 + 2],
                      bf[4 * nt2 + 3], bb + TSW(n, c0 + b_cq));
            }
            unsigned af[2][4];
#pragma unroll
            for (int mt = 0; mt < 2; mt++) {
                int r = wm * 32 + mt * 16 + a_r;
                ldsm4(af[mt][0], af[mt][1], af[mt][2], af[mt][3],
                      sb + TSW(r, c0 + a_cq));
            }
#pragma unroll
            for (int mt = 0; mt < 2; mt++)
#pragma unroll
                for (int nt = 0; nt < 4; nt++)
                    mma16816(acc[mt][nt], af[mt],
                             bf[(nt >> 1) * 4 + (nt & 1) * 2],
                             bf[(nt >> 1) * 4 + (nt & 1) * 2 + 1]);
        }

        int qb = q0 + ch * 128 + wn * 32 + 2 * (lane & 3);
#pragma unroll
        for (int mt = 0; mt < 2; mt++)
#pragma unroll
            for (int p = 0; p < 2; p++) {
                int s = mt * 2 + p;
                float m0 = fmaxf(acc[mt][0][p * 2], acc[mt][0][p * 2 + 1]);
                float m1 = fmaxf(acc[mt][1][p * 2], acc[mt][1][p * 2 + 1]);
                float m2 = fmaxf(acc[mt][2][p * 2], acc[mt][2][p * 2 + 1]);
                float m3 = fmaxf(acc[mt][3][p * 2], acc[mt][3][p * 2 + 1]);
                float vmax = fmaxf(fmaxf(m0, m1), fmaxf(m2, m3));
                float thr = fmaxf(best[s], T0) - DELTA;
                if (vmax > best[s]) best[s] = vmax;
                if (vmax > thr) {
                    int row = rowbase + wm * 32 + mt * 16 + p * 8 + (lane >> 2);
#pragma unroll
                    for (int nt = 0; nt < 4; nt++)
#pragma unroll
                        for (int e = 0; e < 2; e++) {
                            float v = acc[mt][nt][p * 2 + e];
                            if (v > thr) {
                                int col = qb + nt * 8 + e;
                                int slot = atomicAdd(&g_cnt[row], 1);
                                if (slot < CAP) g_cand[row * CAP + slot] = col;
                            }
                        }
                }
            }
    }

#pragma unroll
    for (int s = 0; s < 4; s++) {
        float b = best[s];
#pragma unroll
        for (int off = 1; off <= 2; off <<= 1)
            b = fmaxf(b, __shfl_xor_sync(0xffffffffu, b, off));
        if ((lane & 3) == 0) {
            int row = rowbase + wm * 32 + (s >> 1) * 16 + (s & 1) * 8 + (lane >> 2);
            atomicMax(&g_bestu[row], ford(b));
        }
    }
}

// ---------------------------------------------------------------------------
// 4) rescore (verify merged): per row, flag-or-rescore
// ---------------------------------------------------------------------------
__global__ __launch_bounds__(256) void rescore_kernel(const float* __restrict__ queue) {
    int lane = threadIdx.x & 31, wid = threadIdx.x >> 5;
    int row = blockIdx.x * 8 + wid;
    int cnt = g_cnt[row];
    float A = unford(g_bestu[row]);
    if (cnt == 0 || cnt > CAP || A < T0) {
        if (lane == 0) {
            int slot = atomicAdd(&g_nflag, 1);
            if (slot < MAXFLAG) { g_flaglist[slot] = row; g_fbkey[slot] = 0ull; }
            g_idx[row] = 0;     // fixup overwrites after fallback
        }
        return;
    }
    float4 p = ((const float4*)(g_P + (size_t)row * D))[lane];
    unsigned long long bkey = 0ull;
    for (int i = 0; i < cnt; i++) {
        int col = g_cand[row * CAP + i];
        float4 q = ((const float4*)(queue + (size_t)col * D))[lane];
        float d = fmaf(p.x, q.x, fmaf(p.y, q.y, fmaf(p.z, q.z, p.w * q.w)));
#pragma unroll
        for (int off = 16; off > 0; off >>= 1)
            d += __shfl_xor_sync(0xffffffffu, d, off);
        unsigned long long key =
            ((unsigned long long)ford(d) << 32) |
            (unsigned long long)(0xFFFFFFFFu - (unsigned)col);
        if (key > bkey) bkey = key;
    }
    if (lane == 0)
        g_idx[row] = (int)(0xFFFFFFFFu - (unsigned)(bkey & 0xFFFFFFFFull));
}

// ---------------------------------------------------------------------------
// 5) exact fp32 full-scan fallback, grouped
// ---------------------------------------------------------------------------
__global__ __launch_bounds__(256, 1)
void fallback_kernel(const float* __restrict__ queue) {
    int nf = g_nflag;
    if (nf == 0) return;
    if (nf > MAXFLAG) nf = MAXFLAG;

    extern __shared__ float fsm[];
    __shared__ unsigned long long skey[64];

    int q = blockIdx.x * 256 + threadIdx.x;
    float4 qr[32];
    const float4* qp = (const float4*)(queue + (size_t)q * D);
#pragma unroll
    for (int i = 0; i < 32; i++) qr[i] = qp[i];

    for (int base = 0; base < nf; base += 64) {
        int gsz = min(64, nf - base);
        __syncthreads();
        for (int i = threadIdx.x; i < gsz * 128; i += 256)
            fsm[i] = g_P[(size_t)g_flaglist[base + (i >> 7)] * D + (i & 127)];
        for (int i = threadIdx.x; i < gsz; i += 256) skey[i] = 0ull;
        __syncthreads();

        for (int f = 0; f < gsz; f++) {
            const float4* pr = (const float4*)(fsm + f * 128);
            float s0 = 0.f, s1 = 0.f, s2 = 0.f, s3 = 0.f;
#pragma unroll
            for (int i = 0; i < 32; i++) {
                float4 p = pr[i];
                s0 = fmaf(qr[i].x, p.x, s0);
                s1 = fmaf(qr[i].y, p.y, s1);
                s2 = fmaf(qr[i].z, p.z, s2);
                s3 = fmaf(qr[i].w, p.w, s3);
            }
            float dot = (s0 + s1) + (s2 + s3);
            unsigned long long key =
                ((unsigned long long)ford(dot) << 32) |
                (unsigned long long)(0xFFFFFFFFu - (unsigned)q);
#pragma unroll
            for (int off = 16; off > 0; off >>= 1) {
                unsigned long long o = __shfl_xor_sync(0xffffffffu, key, off);
                if (o > key) key = o;
            }
            if ((threadIdx.x & 31) == 0) atomicMax(&skey[f], key);
        }
        __syncthreads();
        for (int f = threadIdx.x; f < gsz; f += 256)
            atomicMax(&g_fbkey[base + f], skey[f]);
    }
}

__global__ void fixup_kernel() {
    int nf = g_nflag;
    if (nf > MAXFLAG) nf = MAXFLAG;
    int s = blockIdx.x * blockDim.x + threadIdx.x;
    if (s < nf)
        g_idx[g_flaglist[s]] =
            (int)(0xFFFFFFFFu - (unsigned)(g_fbkey[s] & 0xFFFFFFFFull));
}

// ---------------------------------------------------------------------------
// 6) gather NN rows + fused diag logit
// ---------------------------------------------------------------------------
__global__ void gather_kernel(const float* __restrict__ queue, int B, float invT) {
    int row = blockIdx.x, l = threadIdx.x;
    unsigned idx = (unsigned)g_idx[row];
    if (idx >= 65536u) idx = 0u;
    float4 a = ((const float4*)queue)[(size_t)idx * 32 + l];
    ((float4*)g_NN)[(size_t)row * 32 + l] = a;
    int other = (row < B) ? (B + row) : (row - B);
    float4 b = ((const float4*)(g_P + (size_t)other * D))[l];
    float d = fmaf(a.x, b.x, fmaf(a.y, b.y, fmaf(a.z, b.z, a.w * b.w)));
#pragma unroll
    for (int off = 16; off > 0; off >>= 1)
        d += __shfl_xor_sync(0xffffffffu, d, off);
    if (l == 0) g_diag[row] = d * invT;
}

// ---------------------------------------------------------------------------
// fp32 register-tile GEMM with fused exp row/col sums (proven 128x128)
// ---------------------------------------------------------------------------
__device__ __forceinline__ void load_tile_sw(const float* __restrict__ src,
                                             float* sm, int tid) {
    int w = tid >> 5, l = tid & 31;
#pragma unroll
    for (int m = 0; m < 16; m++) {
        int r = w + m * 8;
        float4 v = *(const float4*)(src + (size_t)r * D + 4 * l);
        int slot = (((r >> 2) ^ l) << 2) + (r & 3);
        sm[(4 * l + 0) * 128 + slot] = v.x;
        sm[(4 * l + 1) * 128 + slot] = v.y;
        sm[(4 * l + 2) * 128 + slot] = v.z;
        sm[(4 * l + 3) * 128 + slot] = v.w;
    }
}

__device__ __forceinline__ void mm_tile(const float* sp, const float* sq,
                                        int tx, int ty, float c[8][8]) {
    const float4* sp4 = (const float4*)sp;
    const float4* sq4 = (const float4*)sq;
#pragma unroll 4
    for (int k = 0; k < 128; k++) {
        int s = (k >> 2) & 31;
        float4 A0 = sp4[k * 32 + (ty ^ s)];
        float4 A1 = sp4[k * 32 + ((ty + 16) ^ s)];
        float4 B0 = sq4[k * 32 + (tx ^ s)];
        float4 B1 = sq4[k * 32 + ((tx + 16) ^ s)];
        float a[8] = {A0.x, A0.y, A0.z, A0.w, A1.x, A1.y, A1.z, A1.w};
        float b[8] = {B0.x, B0.y, B0.z, B0.w, B1.x, B1.y, B1.z, B1.w};
#pragma unroll
        for (int i = 0; i < 8; i++)
#pragma unroll
            for (int j = 0; j < 8; j++)
                c[i][j] = fmaf(a[i], b[j], c[i][j]);
    }
}

__global__ __launch_bounds__(256) void gemm_lse_kernel(int B, float invT) {
    extern __shared__ float smemf[];
    float* sp = smemf;
    float* sq = smemf + 128 * 128;
    __shared__ float racc[128], cacc[128];
    int tid = threadIdx.x, tx = tid & 15, ty = tid >> 4;
    int lane = tid & 31;
    int z = blockIdx.z;

    const float* A = g_NN + (size_t)(z * B + blockIdx.x * 128) * D;
    const float* Bm = g_P + (size_t)((z ? 0 : B) + blockIdx.y * 128) * D;

    load_tile_sw(A, sp, tid);
    load_tile_sw(Bm, sq, tid);
    if (tid < 128) { racc[tid] = 0.f; cacc[tid] = 0.f; }
    __syncthreads();

    float c[8][8];
#pragma unroll
    for (int i = 0; i < 8; i++)
#pragma unroll
        for (int j = 0; j < 8; j++) c[i][j] = 0.f;

    mm_tile(sp, sq, tx, ty, c);

    float rsum[8], csum[8];
#pragma unroll
    for (int i = 0; i < 8; i++) { rsum[i] = 0.f; csum[i] = 0.f; }
#pragma unroll
    for (int i = 0; i < 8; i++)
#pragma unroll
        for (int j = 0; j < 8; j++) {
            float e = __expf(c[i][j] * invT);
            rsum[i] += e;
            csum[j] += e;
        }

#pragma unroll
    for (int i = 0; i < 8; i++) {
#pragma unroll
        for (int off = 1; off <= 8; off <<= 1)
            rsum[i] += __shfl_xor_sync(0xffffffffu, rsum[i], off);
        csum[i] += __shfl_xor_sync(0xffffffffu, csum[i], 16);
    }
    if (tx == 0) {
#pragma unroll
        for (int i = 0; i < 8; i++) {
            int r = (i < 4) ? (4 * ty + i) : (64 + 4 * ty + i - 4);
            racc[r] = rsum[i];
        }
    }
    if (lane < 16) {
#pragma unroll
        for (int j = 0; j < 8; j++) {
            int cc = (j < 4) ? (4 * tx + j) : (64 + 4 * tx + j - 4);
            atomicAdd(&cacc[cc], csum[j]);
        }
    }
    __syncthreads();

    if (tid < 128) {
        atomicAdd(&g_S[2 * B * z + blockIdx.x * 128 + tid], racc[tid]);
        atomicAdd(&g_S[2 * B * z + B + blockIdx.y * 128 + tid], cacc[tid]);
    }
}

// ---------------------------------------------------------------------------
// 7) final loss
// ---------------------------------------------------------------------------
__global__ void loss_kernel(float* __restrict__ out, int B) {
    int r = blockIdx.x * blockDim.x + threadIdx.x;
    int di = ((r >= 2 * B) ? B : 0) + (r % B);
    out[r] = logf(g_S[r]) - g_diag[di];
}

// ---------------------------------------------------------------------------
extern "C" void kernel_launch(void* const* d_in, const int* in_sizes, int n_in,
                              void* d_out, int out_size) {
    const float* p1 = (const float*)d_in[0];
    const float* p2 = (const float*)d_in[1];
    const float* queue = (const float*)d_in[2];
    int B = in_sizes[0] / D;     // 2048
    int Q = in_sizes[2] / D;     // 65536
    int BALL = 2 * B;
    float* out = (float*)d_out;

    cudaFuncSetAttribute(nn_kernel,
                         cudaFuncAttributeMaxDynamicSharedMemorySize, SMEM_NN);
    cudaFuncSetAttribute(fallback_kernel,
                         cudaFuncAttributeMaxDynamicSharedMemorySize, 32768);
    cudaFuncSetAttribute(gemm_lse_kernel,
                         cudaFuncAttributeMaxDynamicSharedMemorySize, 131072);

    normalize_kernel<<<BALL, 32>>>(p1, p2, B);
    convq_kernel<<<(Q * D / 4) / 256, 256>>>(queue);

    int rps = Q / NSPLIT;
    nn_kernel<<<dim3(BALL / 64, NSPLIT), 256, SMEM_NN>>>(rps);

    rescore_kernel<<<BALL / 8, 256>>>(queue);
    fallback_kernel<<<Q / 256, 256, 32768>>>(queue);
    fixup_kernel<<<2, 256>>>();
    gather_kernel<<<BALL, 32>>>(queue, B, 10.0f);

    gemm_lse_kernel<<<dim3(B / 128, B / 128, 2), 256, 131072>>>(B, 10.0f);

    loss_kernel<<<4 * B / 256, 256>>>(out, B);
}

// round 16
// speedup vs baseline: 1.5063x; 1.5063x over previous
#include <cuda_runtime.h>
#include <cuda_fp16.h>
#include <math.h>

#define D 128
#define NSPLIT 32
#define CAP 128
#define MAXFLAG 512
#define T0 0.30f
#define DELTA 3e-3f        // >= 2*e for fp16 screen with fp32 accum

// ---- static scratch ----
__device__ float g_P[4096 * 128];
__device__ __half g_Ah[4096 * 128];
__device__ __half g_Qh[65536 * 128];
__device__ float g_NN[4096 * 128];
__device__ int      g_cand[4096 * CAP];
__device__ int      g_cnt[4096];
__device__ unsigned g_bestu[4096];
__device__ int   g_idx[4096];
__device__ int   g_nflag;
__device__ int   g_flaglist[MAXFLAG];
__device__ unsigned long long g_fbkeyrow[4096];
__device__ float g_S[16384];
__device__ float g_diag[4096];

#define TSW(r, c) (((r) * 256) + ((((c) ^ ((r) & 7))) << 4))

__device__ __forceinline__ unsigned smem_u32(const void* p) {
    unsigned a;
    asm("{ .reg .u64 t; cvta.to.shared.u64 t, %1; cvt.u32.u64 %0, t; }"
        : "=r"(a) : "l"(p));
    return a;
}
__device__ __forceinline__ void cp_async16(unsigned sm, const void* g) {
    asm volatile("cp.async.cg.shared.global [%0], [%1], 16;" :: "r"(sm), "l"(g));
}
__device__ __forceinline__ void cp_commit() {
    asm volatile("cp.async.commit_group;");
}
__device__ __forceinline__ void ldsm4(unsigned& r0, unsigned& r1, unsigned& r2,
                                      unsigned& r3, unsigned addr) {
    asm volatile("ldmatrix.sync.aligned.m8n8.x4.shared.b16 {%0,%1,%2,%3}, [%4];"
                 : "=r"(r0), "=r"(r1), "=r"(r2), "=r"(r3) : "r"(addr));
}
__device__ __forceinline__ void mma16816(float c[4], const unsigned a[4],
                                         unsigned b0, unsigned b1) {
    asm volatile("mma.sync.aligned.m16n8k16.row.col.f32.f16.f16.f32 "
                 "{%0,%1,%2,%3}, {%4,%5,%6,%7}, {%8,%9}, {%0,%1,%2,%3};"
                 : "+f"(c[0]), "+f"(c[1]), "+f"(c[2]), "+f"(c[3])
                 : "r"(a[0]), "r"(a[1]), "r"(a[2]), "r"(a[3]), "r"(b0), "r"(b1));
}
__device__ __forceinline__ unsigned ford(float f) {
    unsigned u = __float_as_uint(f);
    return (u & 0x80000000u) ? ~u : (u | 0x80000000u);
}
__device__ __forceinline__ float unford(unsigned k) {
    unsigned u = (k & 0x80000000u) ? (k ^ 0x80000000u) : ~k;
    return __uint_as_float(u);
}

// ---------------------------------------------------------------------------
// 1) normalize -> g_P fp32 + g_Ah fp16
// ---------------------------------------------------------------------------
__global__ void normalize_kernel(const float* __restrict__ p1,
                                 const float* __restrict__ p2, int B) {
    int row = blockIdx.x, l = threadIdx.x;
    const float* src = (row < B) ? (p1 + (size_t)row * D)
                                 : (p2 + (size_t)(row - B) * D);
    float4 v = ((const float4*)src)[l];
    float ss = v.x * v.x + v.y * v.y + v.z * v.z + v.w * v.w;
#pragma unroll
    for (int off = 16; off > 0; off >>= 1)
        ss += __shfl_xor_sync(0xffffffffu, ss, off);
    float inv = 1.0f / sqrtf(ss);
    float4 o = make_float4(v.x * inv, v.y * inv, v.z * inv, v.w * inv);
    ((float4*)g_P)[(size_t)row * 32 + l] = o;
    __half h[4] = {__float2half(o.x), __float2half(o.y),
                   __float2half(o.z), __float2half(o.w)};
    *(uint2*)(g_Ah + (size_t)row * D + 4 * l) = *(uint2*)h;
}

// ---------------------------------------------------------------------------
// 2) queue -> fp16, with per-call state re-init folded into blocks [0,64)
// ---------------------------------------------------------------------------
__global__ void convq_kernel(const float* __restrict__ queue) {
    int i = blockIdx.x * blockDim.x + threadIdx.x;
    if (blockIdx.x < 64) {
        int j = blockIdx.x * 256 + threadIdx.x;      // 0..16383
        g_S[j] = 0.f;
        if (j < 4096) { g_cnt[j] = 0; g_bestu[j] = 0u; }
        if (j == 0) g_nflag = 0;
    }
    float4 v = ((const float4*)queue)[i];
    __half h[4] = {__float2half(v.x), __float2half(v.y),
                   __float2half(v.z), __float2half(v.w)};
    *(uint2*)(g_Qh + 4 * (size_t)i) = *(uint2*)h;
}

// ---------------------------------------------------------------------------
// 3) NN screen: fp16 HMMA fp32-accum, M=64 tile, 3-buffer, fine splits
// ---------------------------------------------------------------------------
#define ABUF 16384
#define BUFSZ 32768
#define SMEM_NN (ABUF + 3 * BUFSZ)      // 114688

__global__ __launch_bounds__(256, 2)
void nn_kernel(int rps) {
    extern __shared__ char smem[];
    unsigned sb = smem_u32(smem);
    int tid = threadIdx.x, lane = tid & 31, wid = tid >> 5;
    int wm = wid >> 2, wn = wid & 3;
    int rowbase = blockIdx.x * 64;
    int q0 = blockIdx.y * rps;
    int nch = rps >> 7;

    int brow = tid >> 1, bh = tid & 1;
    auto issueB = [&](int ch) {
        unsigned bdst = sb + ABUF + (unsigned)(ch % 3) * BUFSZ;
        const __half* qh = g_Qh + (size_t)(q0 + ch * 128 + brow) * D;
#pragma unroll
        for (int i = 0; i < 8; i++) {
            int c = 8 * bh + i;
            cp_async16(bdst + TSW(brow, c), qh + c * 8);
        }
        cp_commit();
    };
    issueB(0);
    issueB(1);

    {
        int r = tid >> 2, qid = tid & 3;
        const uint4* sh = (const uint4*)(g_Ah + (size_t)(rowbase + r) * D);
#pragma unroll
        for (int i = 0; i < 4; i++) {
            int c = 4 * qid + i;
            *(uint4*)(smem + TSW(r, c)) = sh[c];
        }
    }

    float best[4];
#pragma unroll
    for (int s = 0; s < 4; s++) best[s] = -INFINITY;

    int a_r = ((lane >> 3) & 1) * 8 + (lane & 7);
    int a_cq = lane >> 4;
    int b_r = ((lane >> 4) << 3) + (lane & 7);
    int b_cq = (lane >> 3) & 1;

    for (int ch = 0; ch < nch; ch++) {
        if (ch + 1 < nch) asm volatile("cp.async.wait_group 1;");
        else              asm volatile("cp.async.wait_group 0;");
        __syncthreads();
        if (ch + 2 < nch) issueB(ch + 2);

        unsigned bb = sb + ABUF + (unsigned)(ch % 3) * BUFSZ;

        float acc[2][4][4];
#pragma unroll
        for (int mt = 0; mt < 2; mt++)
#pragma unroll
            for (int nt = 0; nt < 4; nt++)
#pragma unroll
                for (int e = 0; e < 4; e++) acc[mt][nt][e] = 0.f;

#pragma unroll
        for (int ks = 0; ks < 8; ks++) {
            int c0 = 2 * ks;
            unsigned bf[8];
#pragma unroll
            for (int nt2 = 0; nt2 < 2; nt2++) {
                int n = wn * 32 + nt2 * 16 + b_r;
                ldsm4(bf[4 * nt2], bf[4 * nt2 + 1], bf[4 * nt2 + 2],
                      bf[4 * nt2 + 3], bb + TSW(n, c0 + b_cq));
            }
            unsigned af[2][4];
#pragma unroll
            for (int mt = 0; mt < 2; mt++) {
                int r = wm * 32 + mt * 16 + a_r;
                ldsm4(af[mt][0], af[mt][1], af[mt][2], af[mt][3],
                      sb + TSW(r, c0 + a_cq));
            }
#pragma unroll
            for (int mt = 0; mt < 2; mt++)
#pragma unroll
                for (int nt = 0; nt < 4; nt++)
                    mma16816(acc[mt][nt], af[mt],
                             bf[(nt >> 1) * 4 + (nt & 1) * 2],
                             bf[(nt >> 1) * 4 + (nt & 1) * 2 + 1]);
        }

        int qb = q0 + ch * 128 + wn * 32 + 2 * (lane & 3);
#pragma unroll
        for (int mt = 0; mt < 2; mt++)
#pragma unroll
            for (int p = 0; p < 2; p++) {
                int s = mt * 2 + p;
                float m0 = fmaxf(acc[mt][0][p * 2], acc[mt][0][p * 2 + 1]);
                float m1 = fmaxf(acc[mt][1][p * 2], acc[mt][1][p * 2 + 1]);
                float m2 = fmaxf(acc[mt][2][p * 2], acc[mt][2][p * 2 + 1]);
                float m3 = fmaxf(acc[mt][3][p * 2], acc[mt][3][p * 2 + 1]);
                float vmax = fmaxf(fmaxf(m0, m1), fmaxf(m2, m3));
                float thr = fmaxf(best[s], T0) - DELTA;
                if (vmax > best[s]) best[s] = vmax;
                if (vmax > thr) {
                    int row = rowbase + wm * 32 + mt * 16 + p * 8 + (lane >> 2);
#pragma unroll
                    for (int nt = 0; nt < 4; nt++)
#pragma unroll
                        for (int e = 0; e < 2; e++) {
                            float v = acc[mt][nt][p * 2 + e];
                            if (v > thr) {
                                int col = qb + nt * 8 + e;
                                int slot = atomicAdd(&g_cnt[row], 1);
                                if (slot < CAP) g_cand[row * CAP + slot] = col;
                            }
                        }
                }
            }
    }

#pragma unroll
    for (int s = 0; s < 4; s++) {
        float b = best[s];
#pragma unroll
        for (int off = 1; off <= 2; off <<= 1)
            b = fmaxf(b, __shfl_xor_sync(0xffffffffu, b, off));
        if ((lane & 3) == 0) {
            int row = rowbase + wm * 32 + (s >> 1) * 16 + (s & 1) * 8 + (lane >> 2);
            atomicMax(&g_bestu[row], ford(b));
        }
    }
}

// ---------------------------------------------------------------------------
// 4) rescore (verify merged): per row, flag-or-rescore
//    flagged rows get g_idx = -1 sentinel; gather resolves from g_fbkeyrow
// ---------------------------------------------------------------------------
__global__ __launch_bounds__(256) void rescore_kernel(const float* __restrict__ queue) {
    int lane = threadIdx.x & 31, wid = threadIdx.x >> 5;
    int row = blockIdx.x * 8 + wid;
    int cnt = g_cnt[row];
    float A = unford(g_bestu[row]);
    if (cnt == 0 || cnt > CAP || A < T0) {
        if (lane == 0) {
            int slot = atomicAdd(&g_nflag, 1);
            if (slot < MAXFLAG) { g_flaglist[slot] = row; g_fbkeyrow[row] = 0ull; }
            g_idx[row] = -1;    // sentinel: resolve via g_fbkeyrow in gather
        }
        return;
    }
    float4 p = ((const float4*)(g_P + (size_t)row * D))[lane];
    unsigned long long bkey = 0ull;
    for (int i = 0; i < cnt; i++) {
        int col = g_cand[row * CAP + i];
        float4 q = ((const float4*)(queue + (size_t)col * D))[lane];
        float d = fmaf(p.x, q.x, fmaf(p.y, q.y, fmaf(p.z, q.z, p.w * q.w)));
#pragma unroll
        for (int off = 16; off > 0; off >>= 1)
            d += __shfl_xor_sync(0xffffffffu, d, off);
        unsigned long long key =
            ((unsigned long long)ford(d) << 32) |
            (unsigned long long)(0xFFFFFFFFu - (unsigned)col);
        if (key > bkey) bkey = key;
    }
    if (lane == 0)
        g_idx[row] = (int)(0xFFFFFFFFu - (unsigned)(bkey & 0xFFFFFFFFull));
}

// ---------------------------------------------------------------------------
// 5) exact fp32 full-scan fallback, grouped, row-indexed keys
// ---------------------------------------------------------------------------
__global__ __launch_bounds__(256, 1)
void fallback_kernel(const float* __restrict__ queue) {
    int nf = g_nflag;
    if (nf == 0) return;
    if (nf > MAXFLAG) nf = MAXFLAG;

    extern __shared__ float fsm[];
    __shared__ unsigned long long skey[64];

    int q = blockIdx.x * 256 + threadIdx.x;
    float4 qr[32];
    const float4* qp = (const float4*)(queue + (size_t)q * D);
#pragma unroll
    for (int i = 0; i < 32; i++) qr[i] = qp[i];

    for (int base = 0; base < nf; base += 64) {
        int gsz = min(64, nf - base);
        __syncthreads();
        for (int i = threadIdx.x; i < gsz * 128; i += 256)
            fsm[i] = g_P[(size_t)g_flaglist[base + (i >> 7)] * D + (i & 127)];
        for (int i = threadIdx.x; i < gsz; i += 256) skey[i] = 0ull;
        __syncthreads();

        for (int f = 0; f < gsz; f++) {
            const float4* pr = (const float4*)(fsm + f * 128);
            float s0 = 0.f, s1 = 0.f, s2 = 0.f, s3 = 0.f;
#pragma unroll
            for (int i = 0; i < 32; i++) {
                float4 p = pr[i];
                s0 = fmaf(qr[i].x, p.x, s0);
                s1 = fmaf(qr[i].y, p.y, s1);
                s2 = fmaf(qr[i].z, p.z, s2);
                s3 = fmaf(qr[i].w, p.w, s3);
            }
            float dot = (s0 + s1) + (s2 + s3);
            unsigned long long key =
                ((unsigned long long)ford(dot) << 32) |
                (unsigned long long)(0xFFFFFFFFu - (unsigned)q);
#pragma unroll
            for (int off = 16; off > 0; off >>= 1) {
                unsigned long long o = __shfl_xor_sync(0xffffffffu, key, off);
                if (o > key) key = o;
            }
            if ((threadIdx.x & 31) == 0) atomicMax(&skey[f], key);
        }
        __syncthreads();
        for (int f = threadIdx.x; f < gsz; f += 256)
            atomicMax(&g_fbkeyrow[g_flaglist[base + f]], skey[f]);
    }
}

// ---------------------------------------------------------------------------
// 6) gather NN rows + fused diag logit + flagged-row fixup
// ---------------------------------------------------------------------------
__global__ void gather_kernel(const float* __restrict__ queue, int B, float invT) {
    int row = blockIdx.x, l = threadIdx.x;
    unsigned idx = (unsigned)g_idx[row];
    if (idx >= 65536u) {   // flagged: resolve from fallback key
        unsigned long long k = g_fbkeyrow[row];
        idx = 0xFFFFFFFFu - (unsigned)(k & 0xFFFFFFFFull);
        if (idx >= 65536u) idx = 0u;   // safety (flag overflow)
    }
    float4 a = ((const float4*)queue)[(size_t)idx * 32 + l];
    ((float4*)g_NN)[(size_t)row * 32 + l] = a;
    int other = (row < B) ? (B + row) : (row - B);
    float4 b = ((const float4*)(g_P + (size_t)other * D))[l];
    float d = fmaf(a.x, b.x, fmaf(a.y, b.y, fmaf(a.z, b.z, a.w * b.w)));
#pragma unroll
    for (int off = 16; off > 0; off >>= 1)
        d += __shfl_xor_sync(0xffffffffu, d, off);
    if (l == 0) g_diag[row] = d * invT;
}

// ---------------------------------------------------------------------------
// fp32 register-tile GEMM with fused exp row/col sums (proven 128x128)
// ---------------------------------------------------------------------------
__device__ __forceinline__ void load_tile_sw(const float* __restrict__ src,
                                             float* sm, int tid) {
    int w = tid >> 5, l = tid & 31;
#pragma unroll
    for (int m = 0; m < 16; m++) {
        int r = w + m * 8;
        float4 v = *(const float4*)(src + (size_t)r * D + 4 * l);
        int slot = (((r >> 2) ^ l) << 2) + (r & 3);
        sm[(4 * l + 0) * 128 + slot] = v.x;
        sm[(4 * l + 1) * 128 + slot] = v.y;
        sm[(4 * l + 2) * 128 + slot] = v.z;
        sm[(4 * l + 3) * 128 + slot] = v.w;
    }
}

__device__ __forceinline__ void mm_tile(const float* sp, const float* sq,
                                        int tx, int ty, float c[8][8]) {
    const float4* sp4 = (const float4*)sp;
    const float4* sq4 = (const float4*)sq;
#pragma unroll 4
    for (int k = 0; k < 128; k++) {
        int s = (k >> 2) & 31;
        float4 A0 = sp4[k * 32 + (ty ^ s)];
        float4 A1 = sp4[k * 32 + ((ty + 16) ^ s)];
        float4 B0 = sq4[k * 32 + (tx ^ s)];
        float4 B1 = sq4[k * 32 + ((tx + 16) ^ s)];
        float a[8] = {A0.x, A0.y, A0.z, A0.w, A1.x, A1.y, A1.z, A1.w};
        float b[8] = {B0.x, B0.y, B0.z, B0.w, B1.x, B1.y, B1.z, B1.w};
#pragma unroll
        for (int i = 0; i < 8; i++)
#pragma unroll
            for (int j = 0; j < 8; j++)
                c[i][j] = fmaf(a[i], b[j], c[i][j]);
    }
}

__global__ __launch_bounds__(256) void gemm_lse_kernel(int B, float invT) {
    extern __shared__ float smemf[];
    float* sp = smemf;
    float* sq = smemf + 128 * 128;
    __shared__ float racc[128], cacc[128];
    int tid = threadIdx.x, tx = tid & 15, ty = tid >> 4;
    int lane = tid & 31;
    int z = blockIdx.z;

    const float* A = g_NN + (size_t)(z * B + blockIdx.x * 128) * D;
    const float* Bm = g_P + (size_t)((z ? 0 : B) + blockIdx.y * 128) * D;

    load_tile_sw(A, sp, tid);
    load_tile_sw(Bm, sq, tid);
    if (tid < 128) { racc[tid] = 0.f; cacc[tid] = 0.f; }
    __syncthreads();

    float c[8][8];
#pragma unroll
    for (int i = 0; i < 8; i++)
#pragma unroll
        for (int j = 0; j < 8; j++) c[i][j] = 0.f;

    mm_tile(sp, sq, tx, ty, c);

    float rsum[8], csum[8];
#pragma unroll
    for (int i = 0; i < 8; i++) { rsum[i] = 0.f; csum[i] = 0.f; }
#pragma unroll
    for (int i = 0; i < 8; i++)
#pragma unroll
        for (int j = 0; j < 8; j++) {
            float e = __expf(c[i][j] * invT);
            rsum[i] += e;
            csum[j] += e;
        }

#pragma unroll
    for (int i = 0; i < 8; i++) {
#pragma unroll
        for (int off = 1; off <= 8; off <<= 1)
            rsum[i] += __shfl_xor_sync(0xffffffffu, rsum[i], off);
        csum[i] += __shfl_xor_sync(0xffffffffu, csum[i], 16);
    }
    if (tx == 0) {
#pragma unroll
        for (int i = 0; i < 8; i++) {
            int r = (i < 4) ? (4 * ty + i) : (64 + 4 * ty + i - 4);
            racc[r] = rsum[i];
        }
    }
    if (lane < 16) {
#pragma unroll
        for (int j = 0; j < 8; j++) {
            int cc = (j < 4) ? (4 * tx + j) : (64 + 4 * tx + j - 4);
            atomicAdd(&cacc[cc], csum[j]);
        }
    }
    __syncthreads();

    if (tid < 128) {
        atomicAdd(&g_S[2 * B * z + blockIdx.x * 128 + tid], racc[tid]);
        atomicAdd(&g_S[2 * B * z + B + blockIdx.y * 128 + tid], cacc[tid]);
    }
}

// ---------------------------------------------------------------------------
// 7) final loss
// ---------------------------------------------------------------------------
__global__ void loss_kernel(float* __restrict__ out, int B) {
    int r = blockIdx.x * blockDim.x + threadIdx.x;
    int di = ((r >= 2 * B) ? B : 0) + (r % B);
    out[r] = logf(g_S[r]) - g_diag[di];
}

// ---------------------------------------------------------------------------
extern "C" void kernel_launch(void* const* d_in, const int* in_sizes, int n_in,
                              void* d_out, int out_size) {
    const float* p1 = (const float*)d_in[0];
    const float* p2 = (const float*)d_in[1];
    const float* queue = (const float*)d_in[2];
    int B = in_sizes[0] / D;     // 2048
    int Q = in_sizes[2] / D;     // 65536
    int BALL = 2 * B;
    float* out = (float*)d_out;

    cudaFuncSetAttribute(nn_kernel,
                         cudaFuncAttributeMaxDynamicSharedMemorySize, SMEM_NN);
    cudaFuncSetAttribute(fallback_kernel,
                         cudaFuncAttributeMaxDynamicSharedMemorySize, 32768);
    cudaFuncSetAttribute(gemm_lse_kernel,
                         cudaFuncAttributeMaxDynamicSharedMemorySize, 131072);

    normalize_kernel<<<BALL, 32>>>(p1, p2, B);
    convq_kernel<<<(Q * D / 4) / 256, 256>>>(queue);

    int rps = Q / NSPLIT;
    nn_kernel<<<dim3(BALL / 64, NSPLIT), 256, SMEM_NN>>>(rps);

    rescore_kernel<<<BALL / 8, 256>>>(queue);
    fallback_kernel<<<Q / 256, 256, 32768>>>(queue);
    gather_kernel<<<BALL, 32>>>(queue, B, 10.0f);

    gemm_lse_kernel<<<dim3(B / 128, B / 128, 2), 256, 131072>>>(B, 10.0f);

    loss_kernel<<<4 * B / 256, 256>>>(out, B);
}

// round 17
// speedup vs baseline: 1.5269x; 1.0136x over previous
#include <cuda_runtime.h>
#include <cuda_fp16.h>
#include <math.h>

#define D 128
#define NSPLIT 32
#define CAP 128
#define MAXFLAG 512
#define T0 0.30f
#define DELTA 3e-3f        // >= 2*e for fp16 screen with fp32 accum

// ---- static scratch ----
__device__ float g_P[4096 * 128];
__device__ __half g_Ah[4096 * 128];
__device__ __half g_Qh[65536 * 128];
__device__ float g_NN[4096 * 128];
__device__ int      g_cand[4096 * CAP];
__device__ int      g_cnt[4096];
__device__ unsigned g_bestu[4096];
__device__ int   g_nflag;
__device__ int   g_flaglist[MAXFLAG];
__device__ unsigned long long g_fbkeyrow[4096];   // per-row best (key-encoded)
__device__ float g_S[16384];
__device__ float g_diag[4096];

#define TSW(r, c) (((r) * 256) + ((((c) ^ ((r) & 7))) << 4))

__device__ __forceinline__ unsigned smem_u32(const void* p) {
    unsigned a;
    asm("{ .reg .u64 t; cvta.to.shared.u64 t, %1; cvt.u32.u64 %0, t; }"
        : "=r"(a) : "l"(p));
    return a;
}
__device__ __forceinline__ void cp_async16(unsigned sm, const void* g) {
    asm volatile("cp.async.cg.shared.global [%0], [%1], 16;" :: "r"(sm), "l"(g));
}
__device__ __forceinline__ void cp_commit() {
    asm volatile("cp.async.commit_group;");
}
__device__ __forceinline__ void ldsm4(unsigned& r0, unsigned& r1, unsigned& r2,
                                      unsigned& r3, unsigned addr) {
    asm volatile("ldmatrix.sync.aligned.m8n8.x4.shared.b16 {%0,%1,%2,%3}, [%4];"
                 : "=r"(r0), "=r"(r1), "=r"(r2), "=r"(r3) : "r"(addr));
}
__device__ __forceinline__ void mma16816(float c[4], const unsigned a[4],
                                         unsigned b0, unsigned b1) {
    asm volatile("mma.sync.aligned.m16n8k16.row.col.f32.f16.f16.f32 "
                 "{%0,%1,%2,%3}, {%4,%5,%6,%7}, {%8,%9}, {%0,%1,%2,%3};"
                 : "+f"(c[0]), "+f"(c[1]), "+f"(c[2]), "+f"(c[3])
                 : "r"(a[0]), "r"(a[1]), "r"(a[2]), "r"(a[3]), "r"(b0), "r"(b1));
}
__device__ __forceinline__ unsigned ford(float f) {
    unsigned u = __float_as_uint(f);
    return (u & 0x80000000u) ? ~u : (u | 0x80000000u);
}
__device__ __forceinline__ float unford(unsigned k) {
    unsigned u = (k & 0x80000000u) ? (k ^ 0x80000000u) : ~k;
    return __uint_as_float(u);
}

// ---------------------------------------------------------------------------
// 1) normalize -> g_P fp32 + g_Ah fp16
// ---------------------------------------------------------------------------
__global__ void normalize_kernel(const float* __restrict__ p1,
                                 const float* __restrict__ p2, int B) {
    int row = blockIdx.x, l = threadIdx.x;
    const float* src = (row < B) ? (p1 + (size_t)row * D)
                                 : (p2 + (size_t)(row - B) * D);
    float4 v = ((const float4*)src)[l];
    float ss = v.x * v.x + v.y * v.y + v.z * v.z + v.w * v.w;
#pragma unroll
    for (int off = 16; off > 0; off >>= 1)
        ss += __shfl_xor_sync(0xffffffffu, ss, off);
    float inv = 1.0f / sqrtf(ss);
    float4 o = make_float4(v.x * inv, v.y * inv, v.z * inv, v.w * inv);
    ((float4*)g_P)[(size_t)row * 32 + l] = o;
    __half h[4] = {__float2half(o.x), __float2half(o.y),
                   __float2half(o.z), __float2half(o.w)};
    *(uint2*)(g_Ah + (size_t)row * D + 4 * l) = *(uint2*)h;
}

// ---------------------------------------------------------------------------
// 2) queue -> fp16, with per-call state re-init folded into blocks [0,64)
// ---------------------------------------------------------------------------
__global__ void convq_kernel(const float* __restrict__ queue) {
    int i = blockIdx.x * blockDim.x + threadIdx.x;
    if (blockIdx.x < 64) {
        int j = blockIdx.x * 256 + threadIdx.x;      // 0..16383
        g_S[j] = 0.f;
        if (j < 4096) {
            g_cnt[j] = 0; g_bestu[j] = 0u; g_fbkeyrow[j] = 0ull;
        }
        if (j == 0) g_nflag = 0;
    }
    float4 v = ((const float4*)queue)[i];
    __half h[4] = {__float2half(v.x), __float2half(v.y),
                   __float2half(v.z), __float2half(v.w)};
    *(uint2*)(g_Qh + 4 * (size_t)i) = *(uint2*)h;
}

// ---------------------------------------------------------------------------
// 3) NN screen: fp16 HMMA fp32-accum, M=64 tile, 3-buffer, fine splits
// ---------------------------------------------------------------------------
#define ABUF 16384
#define BUFSZ 32768
#define SMEM_NN (ABUF + 3 * BUFSZ)      // 114688

__global__ __launch_bounds__(256, 2)
void nn_kernel(int rps) {
    extern __shared__ char smem[];
    unsigned sb = smem_u32(smem);
    int tid = threadIdx.x, lane = tid & 31, wid = tid >> 5;
    int wm = wid >> 2, wn = wid & 3;
    int rowbase = blockIdx.x * 64;
    int q0 = blockIdx.y * rps;
    int nch = rps >> 7;

    int brow = tid >> 1, bh = tid & 1;
    auto issueB = [&](int ch) {
        unsigned bdst = sb + ABUF + (unsigned)(ch % 3) * BUFSZ;
        const __half* qh = g_Qh + (size_t)(q0 + ch * 128 + brow) * D;
#pragma unroll
        for (int i = 0; i < 8; i++) {
            int c = 8 * bh + i;
            cp_async16(bdst + TSW(brow, c), qh + c * 8);
        }
        cp_commit();
    };
    issueB(0);
    issueB(1);

    {
        int r = tid >> 2, qid = tid & 3;
        const uint4* sh = (const uint4*)(g_Ah + (size_t)(rowbase + r) * D);
#pragma unroll
        for (int i = 0; i < 4; i++) {
            int c = 4 * qid + i;
            *(uint4*)(smem + TSW(r, c)) = sh[c];
        }
    }

    float best[4];
#pragma unroll
    for (int s = 0; s < 4; s++) best[s] = -INFINITY;

    int a_r = ((lane >> 3) & 1) * 8 + (lane & 7);
    int a_cq = lane >> 4;
    int b_r = ((lane >> 4) << 3) + (lane & 7);
    int b_cq = (lane >> 3) & 1;

    for (int ch = 0; ch < nch; ch++) {
        if (ch + 1 < nch) asm volatile("cp.async.wait_group 1;");
        else              asm volatile("cp.async.wait_group 0;");
        __syncthreads();
        if (ch + 2 < nch) issueB(ch + 2);

        unsigned bb = sb + ABUF + (unsigned)(ch % 3) * BUFSZ;

        float acc[2][4][4];
#pragma unroll
        for (int mt = 0; mt < 2; mt++)
#pragma unroll
            for (int nt = 0; nt < 4; nt++)
#pragma unroll
                for (int e = 0; e < 4; e++) acc[mt][nt][e] = 0.f;

#pragma unroll
        for (int ks = 0; ks < 8; ks++) {
            int c0 = 2 * ks;
            unsigned bf[8];
#pragma unroll
            for (int nt2 = 0; nt2 < 2; nt2++) {
                int n = wn * 32 + nt2 * 16 + b_r;
                ldsm4(bf[4 * nt2], bf[4 * nt2 + 1], bf[4 * nt2 + 2],
                      bf[4 * nt2 + 3], bb + TSW(n, c0 + b_cq));
            }
            unsigned af[2][4];
#pragma unroll
            for (int mt = 0; mt < 2; mt++) {
                int r = wm * 32 + mt * 16 + a_r;
                ldsm4(af[mt][0], af[mt][1], af[mt][2], af[mt][3],
                      sb + TSW(r, c0 + a_cq));
            }
#pragma unroll
            for (int mt = 0; mt < 2; mt++)
#pragma unroll
                for (int nt = 0; nt < 4; nt++)
                    mma16816(acc[mt][nt], af[mt],
                             bf[(nt >> 1) * 4 + (nt & 1) * 2],
                             bf[(nt >> 1) * 4 + (nt & 1) * 2 + 1]);
        }

        int qb = q0 + ch * 128 + wn * 32 + 2 * (lane & 3);
#pragma unroll
        for (int mt = 0; mt < 2; mt++)
#pragma unroll
            for (int p = 0; p < 2; p++) {
                int s = mt * 2 + p;
                float m0 = fmaxf(acc[mt][0][p * 2], acc[mt][0][p * 2 + 1]);
                float m1 = fmaxf(acc[mt][1][p * 2], acc[mt][1][p * 2 + 1]);
                float m2 = fmaxf(acc[mt][2][p * 2], acc[mt][2][p * 2 + 1]);
                float m3 = fmaxf(acc[mt][3][p * 2], acc[mt][3][p * 2 + 1]);
                float vmax = fmaxf(fmaxf(m0, m1), fmaxf(m2, m3));
                float thr = fmaxf(best[s], T0) - DELTA;
                if (vmax > best[s]) best[s] = vmax;
                if (vmax > thr) {
                    int row = rowbase + wm * 32 + mt * 16 + p * 8 + (lane >> 2);
#pragma unroll
                    for (int nt = 0; nt < 4; nt++)
#pragma unroll
                        for (int e = 0; e < 2; e++) {
                            float v = acc[mt][nt][p * 2 + e];
                            if (v > thr) {
                                int col = qb + nt * 8 + e;
                                int slot = atomicAdd(&g_cnt[row], 1);
                                if (slot < CAP) g_cand[row * CAP + slot] = col;
                            }
                        }
                }
            }
    }

#pragma unroll
    for (int s = 0; s < 4; s++) {
        float b = best[s];
#pragma unroll
        for (int off = 1; off <= 2; off <<= 1)
            b = fmaxf(b, __shfl_xor_sync(0xffffffffu, b, off));
        if ((lane & 3) == 0) {
            int row = rowbase + wm * 32 + (s >> 1) * 16 + (s & 1) * 8 + (lane >> 2);
            atomicMax(&g_bestu[row], ford(b));
        }
    }
}

// ---------------------------------------------------------------------------
// 4) rescore: 2 warps per row, prefetched candidate loop, atomicMax merge
// ---------------------------------------------------------------------------
__global__ __launch_bounds__(256) void rescore_kernel(const float* __restrict__ queue) {
    int lane = threadIdx.x & 31, wid = threadIdx.x >> 5;
    int row = blockIdx.x * 4 + (wid >> 1);
    int half = wid & 1;
    int cnt = g_cnt[row];
    float A = unford(g_bestu[row]);
    if (cnt == 0 || cnt > CAP || A < T0) {
        if (half == 0 && lane == 0) {
            int slot = atomicAdd(&g_nflag, 1);
            if (slot < MAXFLAG) g_flaglist[slot] = row;
            // g_fbkeyrow stays 0; fallback fills it
        }
        return;
    }
    float4 p = ((const float4*)(g_P + (size_t)row * D))[lane];
    unsigned long long bkey = 0ull;

    int i = half;
    float4 q, qn;
    int col = 0, coln = 0;
    if (i < cnt) {
        col = g_cand[row * CAP + i];
        q = ((const float4*)(queue + (size_t)col * D))[lane];
    }
    for (; i < cnt; i += 2) {
        int inext = i + 2;
        if (inext < cnt) {
            coln = g_cand[row * CAP + inext];
            qn = ((const float4*)(queue + (size_t)coln * D))[lane];
        }
        float d = fmaf(p.x, q.x, fmaf(p.y, q.y, fmaf(p.z, q.z, p.w * q.w)));
#pragma unroll
        for (int off = 16; off > 0; off >>= 1)
            d += __shfl_xor_sync(0xffffffffu, d, off);
        unsigned long long key =
            ((unsigned long long)ford(d) << 32) |
            (unsigned long long)(0xFFFFFFFFu - (unsigned)col);
        if (key > bkey) bkey = key;
        q = qn;
        col = coln;
    }
    if (lane == 0 && bkey != 0ull)
        atomicMax(&g_fbkeyrow[row], bkey);
}

// ---------------------------------------------------------------------------
// 5) exact fp32 full-scan fallback, grouped, row-indexed keys
// ---------------------------------------------------------------------------
__global__ __launch_bounds__(256, 1)
void fallback_kernel(const float* __restrict__ queue) {
    int nf = g_nflag;
    if (nf == 0) return;
    if (nf > MAXFLAG) nf = MAXFLAG;

    extern __shared__ float fsm[];
    __shared__ unsigned long long skey[64];

    int q = blockIdx.x * 256 + threadIdx.x;
    float4 qr[32];
    const float4* qp = (const float4*)(queue + (size_t)q * D);
#pragma unroll
    for (int i = 0; i < 32; i++) qr[i] = qp[i];

    for (int base = 0; base < nf; base += 64) {
        int gsz = min(64, nf - base);
        __syncthreads();
        for (int i = threadIdx.x; i < gsz * 128; i += 256)
            fsm[i] = g_P[(size_t)g_flaglist[base + (i >> 7)] * D + (i & 127)];
        for (int i = threadIdx.x; i < gsz; i += 256) skey[i] = 0ull;
        __syncthreads();

        for (int f = 0; f < gsz; f++) {
            const float4* pr = (const float4*)(fsm + f * 128);
            float s0 = 0.f, s1 = 0.f, s2 = 0.f, s3 = 0.f;
#pragma unroll
            for (int i = 0; i < 32; i++) {
                float4 p = pr[i];
                s0 = fmaf(qr[i].x, p.x, s0);
                s1 = fmaf(qr[i].y, p.y, s1);
                s2 = fmaf(qr[i].z, p.z, s2);
                s3 = fmaf(qr[i].w, p.w, s3);
            }
            float dot = (s0 + s1) + (s2 + s3);
            unsigned long long key =
                ((unsigned long long)ford(dot) << 32) |
                (unsigned long long)(0xFFFFFFFFu - (unsigned)q);
#pragma unroll
            for (int off = 16; off > 0; off >>= 1) {
                unsigned long long o = __shfl_xor_sync(0xffffffffu, key, off);
                if (o > key) key = o;
            }
            if ((threadIdx.x & 31) == 0) atomicMax(&skey[f], key);
        }
        __syncthreads();
        for (int f = threadIdx.x; f < gsz; f += 256)
            atomicMax(&g_fbkeyrow[g_flaglist[base + f]], skey[f]);
    }
}

// ---------------------------------------------------------------------------
// 6) gather NN rows + fused diag logit (index decoded from row key)
// ---------------------------------------------------------------------------
__global__ void gather_kernel(const float* __restrict__ queue, int B, float invT) {
    int row = blockIdx.x, l = threadIdx.x;
    unsigned long long k = g_fbkeyrow[row];
    unsigned idx = 0xFFFFFFFFu - (unsigned)(k & 0xFFFFFFFFull);
    if (k == 0ull || idx >= 65536u) idx = 0u;   // safety (flag overflow)
    float4 a = ((const float4*)queue)[(size_t)idx * 32 + l];
    ((float4*)g_NN)[(size_t)row * 32 + l] = a;
    int other = (row < B) ? (B + row) : (row - B);
    float4 b = ((const float4*)(g_P + (size_t)other * D))[l];
    float d = fmaf(a.x, b.x, fmaf(a.y, b.y, fmaf(a.z, b.z, a.w * b.w)));
#pragma unroll
    for (int off = 16; off > 0; off >>= 1)
        d += __shfl_xor_sync(0xffffffffu, d, off);
    if (l == 0) g_diag[row] = d * invT;
}

// ---------------------------------------------------------------------------
// fp32 register-tile GEMM with fused exp row/col sums (proven 128x128)
// ---------------------------------------------------------------------------
__device__ __forceinline__ void load_tile_sw(const float* __restrict__ src,
                                             float* sm, int tid) {
    int w = tid >> 5, l = tid & 31;
#pragma unroll
    for (int m = 0; m < 16; m++) {
        int r = w + m * 8;
        float4 v = *(const float4*)(src + (size_t)r * D + 4 * l);
        int slot = (((r >> 2) ^ l) << 2) + (r & 3);
        sm[(4 * l + 0) * 128 + slot] = v.x;
        sm[(4 * l + 1) * 128 + slot] = v.y;
        sm[(4 * l + 2) * 128 + slot] = v.z;
        sm[(4 * l + 3) * 128 + slot] = v.w;
    }
}

__device__ __forceinline__ void mm_tile(const float* sp, const float* sq,
                                        int tx, int ty, float c[8][8]) {
    const float4* sp4 = (const float4*)sp;
    const float4* sq4 = (const float4*)sq;
#pragma unroll 4
    for (int k = 0; k < 128; k++) {
        int s = (k >> 2) & 31;
        float4 A0 = sp4[k * 32 + (ty ^ s)];
        float4 A1 = sp4[k * 32 + ((ty + 16) ^ s)];
        float4 B0 = sq4[k * 32 + (tx ^ s)];
        float4 B1 = sq4[k * 32 + ((tx + 16) ^ s)];
        float a[8] = {A0.x, A0.y, A0.z, A0.w, A1.x, A1.y, A1.z, A1.w};
        float b[8] = {B0.x, B0.y, B0.z, B0.w, B1.x, B1.y, B1.z, B1.w};
#pragma unroll
        for (int i = 0; i < 8; i++)
#pragma unroll
            for (int j = 0; j < 8; j++)
                c[i][j] = fmaf(a[i], b[j], c[i][j]);
    }
}

__global__ __launch_bounds__(256) void gemm_lse_kernel(int B, float invT) {
    extern __shared__ float smemf[];
    float* sp = smemf;
    float* sq = smemf + 128 * 128;
    __shared__ float racc[128], cacc[128];
    int tid = threadIdx.x, tx = tid & 15, ty = tid >> 4;
    int lane = tid & 31;
    int z = blockIdx.z;

    const float* A = g_NN + (size_t)(z * B + blockIdx.x * 128) * D;
    const float* Bm = g_P + (size_t)((z ? 0 : B) + blockIdx.y * 128) * D;

    load_tile_sw(A, sp, tid);
    load_tile_sw(Bm, sq, tid);
    if (tid < 128) { racc[tid] = 0.f; cacc[tid] = 0.f; }
    __syncthreads();

    float c[8][8];
#pragma unroll
    for (int i = 0; i < 8; i++)
#pragma unroll
        for (int j = 0; j < 8; j++) c[i][j] = 0.f;

    mm_tile(sp, sq, tx, ty, c);

    float rsum[8], csum[8];
#pragma unroll
    for (int i = 0; i < 8; i++) { rsum[i] = 0.f; csum[i] = 0.f; }
#pragma unroll
    for (int i = 0; i < 8; i++)
#pragma unroll
        for (int j = 0; j < 8; j++) {
            float e = __expf(c[i][j] * invT);
            rsum[i] += e;
            csum[j] += e;
        }

#pragma unroll
    for (int i = 0; i < 8; i++) {
#pragma unroll
        for (int off = 1; off <= 8; off <<= 1)
            rsum[i] += __shfl_xor_sync(0xffffffffu, rsum[i], off);
        csum[i] += __shfl_xor_sync(0xffffffffu, csum[i], 16);
    }
    if (tx == 0) {
#pragma unroll
        for (int i = 0; i < 8; i++) {
            int r = (i < 4) ? (4 * ty + i) : (64 + 4 * ty + i - 4);
            racc[r] = rsum[i];
        }
    }
    if (lane < 16) {
#pragma unroll
        for (int j = 0; j < 8; j++) {
            int cc = (j < 4) ? (4 * tx + j) : (64 + 4 * tx + j - 4);
            atomicAdd(&cacc[cc], csum[j]);
        }
    }
    __syncthreads();

    if (tid < 128) {
        atomicAdd(&g_S[2 * B * z + blockIdx.x * 128 + tid], racc[tid]);
        atomicAdd(&g_S[2 * B * z + B + blockIdx.y * 128 + tid], cacc[tid]);
    }
}

// ---------------------------------------------------------------------------
// 7) final loss
// ---------------------------------------------------------------------------
__global__ void loss_kernel(float* __restrict__ out, int B) {
    int r = blockIdx.x * blockDim.x + threadIdx.x;
    int di = ((r >= 2 * B) ? B : 0) + (r % B);
    out[r] = logf(g_S[r]) - g_diag[di];
}

// ---------------------------------------------------------------------------
extern "C" void kernel_launch(void* const* d_in, const int* in_sizes, int n_in,
                              void* d_out, int out_size) {
    const float* p1 = (const float*)d_in[0];
    const float* p2 = (const float*)d_in[1];
    const float* queue = (const float*)d_in[2];
    int B = in_sizes[0] / D;     // 2048
    int Q = in_sizes[2] / D;     // 65536
    int BALL = 2 * B;
    float* out = (float*)d_out;

    cudaFuncSetAttribute(nn_kernel,
                         cudaFuncAttributeMaxDynamicSharedMemorySize, SMEM_NN);
    cudaFuncSetAttribute(fallback_kernel,
                         cudaFuncAttributeMaxDynamicSharedMemorySize, 32768);
    cudaFuncSetAttribute(gemm_lse_kernel,
                         cudaFuncAttributeMaxDynamicSharedMemorySize, 131072);

    normalize_kernel<<<BALL, 32>>>(p1, p2, B);
    convq_kernel<<<(Q * D / 4) / 256, 256>>>(queue);

    int rps = Q / NSPLIT;
    nn_kernel<<<dim3(BALL / 64, NSPLIT), 256, SMEM_NN>>>(rps);

    rescore_kernel<<<BALL / 4, 256>>>(queue);
    fallback_kernel<<<Q / 256, 256, 32768>>>(queue);
    gather_kernel<<<BALL, 32>>>(queue, B, 10.0f);

    gemm_lse_kernel<<<dim3(B / 128, B / 128, 2), 256, 131072>>>(B, 10.0f);

    loss_kernel<<<4 * B / 256, 256>>>(out, B);
}